// round 1
// baseline (speedup 1.0000x reference)
#include <cuda_runtime.h>
#include <cuda_bf16.h>

#define D_MODEL 1024
#define MAX_SEGS 256
#define NBLOCKS 296
#define NTHREADS 256

__device__ float g_seg_sum[MAX_SEGS];

// ---------------------------------------------------------------------------
// Kernel 0: zero output + segment sums
// ---------------------------------------------------------------------------
__global__ void zero_kernel(float* __restrict__ out, int n_out, int nseg) {
    int i = blockIdx.x * blockDim.x + threadIdx.x;
    if (i < n_out) out[i] = 0.0f;
    if (i < nseg)  g_seg_sum[i] = 0.0f;
}

// ---------------------------------------------------------------------------
// Main kernel: one HBM pass over x. Warp-per-token streaming.
// Lane l owns dims {c*128 + 4l + j : c in [0,8), j in [0,4)}.
// ---------------------------------------------------------------------------
__device__ __forceinline__ void flush_seg(float* __restrict__ out, int seg,
                                          const float4* acc, float sump, int lane) {
    float* o = out + (size_t)seg * D_MODEL;
#pragma unroll
    for (int c = 0; c < 8; c++) {
        int base = c * 128 + lane * 4;
        atomicAdd(o + base + 0, acc[c].x);
        atomicAdd(o + base + 1, acc[c].y);
        atomicAdd(o + base + 2, acc[c].z);
        atomicAdd(o + base + 3, acc[c].w);
    }
    if (lane == 0) atomicAdd(&g_seg_sum[seg], sump);
}

__global__ __launch_bounds__(NTHREADS, 2)
void pool_kernel(const float* __restrict__ x,
                 const int*   __restrict__ cu,
                 const float* __restrict__ Wp,
                 const float* __restrict__ bp,
                 float* __restrict__ out,
                 int T, int nseg) {
    const int lane   = threadIdx.x & 31;
    const int gwarp  = (blockIdx.x * blockDim.x + threadIdx.x) >> 5;
    const int nwarps = (gridDim.x * blockDim.x) >> 5;
    const int per    = (T + nwarps - 1) / nwarps;
    const int t0     = gwarp * per;
    const int t1     = min(t0 + per, T);
    if (t0 >= t1) return;

    const float b = bp[0];

    // W stays in registers for the whole kernel (32 floats/lane).
    float4 w[8];
#pragma unroll
    for (int c = 0; c < 8; c++)
        w[c] = *reinterpret_cast<const float4*>(Wp + c * 128 + lane * 4);

    // Find the segment containing t0 (cu is tiny & L2-hot; linear scan fine).
    int seg = 0;
    while (cu[seg + 1] <= t0) seg++;
    int nb = cu[seg + 1];

    float4 acc[8];
#pragma unroll
    for (int c = 0; c < 8; c++) acc[c] = make_float4(0.f, 0.f, 0.f, 0.f);
    float sump = 0.0f;

    for (int t = t0; t < t1; t++) {
        if (t >= nb) {
            flush_seg(out, seg, acc, sump, lane);
#pragma unroll
            for (int c = 0; c < 8; c++) acc[c] = make_float4(0.f, 0.f, 0.f, 0.f);
            sump = 0.0f;
            do { seg++; nb = cu[seg + 1]; } while (t >= nb);
        }

        const float4* row = reinterpret_cast<const float4*>(x + (size_t)t * D_MODEL);

        // Load full 4KB row across the warp (8 coalesced LDG.128 per lane).
        float4 v[8];
#pragma unroll
        for (int c = 0; c < 8; c++) v[c] = row[c * 32 + lane];

        // Dot with W
        float d = 0.0f;
#pragma unroll
        for (int c = 0; c < 8; c++)
            d += v[c].x * w[c].x + v[c].y * w[c].y + v[c].z * w[c].z + v[c].w * w[c].w;
#pragma unroll
        for (int o = 16; o > 0; o >>= 1)
            d += __shfl_xor_sync(0xffffffffu, d, o);

        // Unshifted exp is safe here: |score| <~ 5.5 for N(0,1) scores.
        float p = __expf(d + b);
        sump += p;

#pragma unroll
        for (int c = 0; c < 8; c++) {
            acc[c].x += p * v[c].x;
            acc[c].y += p * v[c].y;
            acc[c].z += p * v[c].z;
            acc[c].w += p * v[c].w;
        }
    }
    flush_seg(out, seg, acc, sump, lane);
}

// ---------------------------------------------------------------------------
// Kernel 2: divide by per-segment sum
// ---------------------------------------------------------------------------
__global__ void norm_kernel(float* __restrict__ out, int n_out) {
    int i = blockIdx.x * blockDim.x + threadIdx.x;
    if (i < n_out) out[i] = out[i] / g_seg_sum[i >> 10];   // D_MODEL == 1024
}

// ---------------------------------------------------------------------------
extern "C" void kernel_launch(void* const* d_in, const int* in_sizes, int n_in,
                              void* d_out, int out_size) {
    const float* x  = (const float*)d_in[0];
    const int*   cu = (const int*)  d_in[1];
    const float* W  = (const float*)d_in[2];
    const float* b  = (const float*)d_in[3];
    float* out = (float*)d_out;

    const int T    = in_sizes[0] / D_MODEL;
    const int nseg = in_sizes[1] - 1;
    const int n_out = nseg * D_MODEL;

    zero_kernel<<<(n_out + 255) / 256, 256>>>(out, n_out, nseg);
    pool_kernel<<<NBLOCKS, NTHREADS>>>(x, cu, W, b, out, T, nseg);
    norm_kernel<<<(n_out + 255) / 256, 256>>>(out, n_out);
}